// round 13
// baseline (speedup 1.0000x reference)
#include <cuda_runtime.h>

// Problem: tet geometry + vertex segment-max.
// Inputs:  d_in[0] vertices  (V=1,000,000 x 3 f32)
//          d_in[1] indices   (T=4,000,000 x 4 i32)
//          d_in[2] tet_density (T f32)
// Output:  d_out = [tet_area (T) | tet_alpha (T) | vert_density (V)] f32
//
// FINAL. Reproduced at 129.50 / 129.60 / 129.09 us (R8/R10/R11).
// Model (validated R2-R11): tet kernel is pinned at the L2 transaction-count
// roofline — 16M divergent 16B gather wavefronts + 16M spread RED.MAX +
// ~4M streaming transactions vs ~184 LTS slices ~= 120us @ ~92% L2 util.
// Session history: 152.1 (scalar gathers) -> 131.9 (float4-padded gathers,
// the one real win: 3x fewer L1 wavefronts, -25% gather sectors) -> 129.1
// (edge tuning). Falsified: L1 policy (R7), coarsening (R9), memset split
// (R4), read-filtered atomics / dedup / compact records / DSMEM (arithmetic).

#define MAX_VERTS 1000000

__device__ float4 g_verts4[MAX_VERTS];

// Prep: pad vertices to float4 AND zero the vert_density output region.
// Each thread: 4 vertices = 3 coalesced float4 loads, 4 float4 stores, 1 zero.
__global__ __launch_bounds__(256) void prep_kernel(const float4* __restrict__ verts4,
                                                   float4* __restrict__ vd4,
                                                   int num_groups) {  // num_verts/4
    int g = blockIdx.x * blockDim.x + threadIdx.x;
    if (g >= num_groups) return;

    float4 a = __ldcs(&verts4[3 * g + 0]);  // v0.x v0.y v0.z v1.x
    float4 b = __ldcs(&verts4[3 * g + 1]);  // v1.y v1.z v2.x v2.y
    float4 c = __ldcs(&verts4[3 * g + 2]);  // v2.z v3.x v3.y v3.z

    g_verts4[4 * g + 0] = make_float4(a.x, a.y, a.z, 0.0f);
    g_verts4[4 * g + 1] = make_float4(a.w, b.x, b.y, 0.0f);
    g_verts4[4 * g + 2] = make_float4(b.z, b.w, c.x, 0.0f);
    g_verts4[4 * g + 3] = make_float4(c.y, c.z, c.w, 0.0f);

    __stcs(&vd4[g], make_float4(0.0f, 0.0f, 0.0f, 0.0f));
}

__global__ __launch_bounds__(256) void tet_kernel(
        const int4* __restrict__ indices,
        const float* __restrict__ tet_density,
        float* __restrict__ tet_area,
        float* __restrict__ tet_alpha,
        int* __restrict__ vert_density_i,  // float bits, all >= 0
        int num_tets) {
    int t = blockIdx.x * blockDim.x + threadIdx.x;
    if (t >= num_tets) return;

    int4 idx = __ldcs(&indices[t]);      // streaming: evict-first
    float d  = __ldcs(&tet_density[t]);  // streaming: evict-first

    // 4 independent 16B gathers -> high MLP, 1 L2 sector each; default policy
    // (policy proven irrelevant in R7; keep L2-resident default).
    float4 v0 = g_verts4[idx.x];
    float4 v1 = g_verts4[idx.y];
    float4 v2 = g_verts4[idx.z];
    float4 v3 = g_verts4[idx.w];

    // det of edge matrix
    float e1x = v1.x - v0.x, e1y = v1.y - v0.y, e1z = v1.z - v0.z;
    float e2x = v2.x - v0.x, e2y = v2.y - v0.y, e2z = v2.z - v0.z;
    float e3x = v3.x - v0.x, e3y = v3.y - v0.y, e3z = v3.z - v0.z;

    float det = e1x * (e2y * e3z - e2z * e3y)
              - e1y * (e2x * e3z - e2z * e3x)
              + e1z * (e2x * e3y - e2y * e3x);
    float area = fabsf(det) * (1.0f / 6.0f);

    // min squared edge length over all 6 edges
    float d01 = e1x * e1x + e1y * e1y + e1z * e1z;
    float d02 = e2x * e2x + e2y * e2y + e2z * e2z;
    float d03 = e3x * e3x + e3y * e3y + e3z * e3z;
    float ax = v1.x - v2.x, ay = v1.y - v2.y, az = v1.z - v2.z;
    float d12 = ax * ax + ay * ay + az * az;
    float bx = v1.x - v3.x, by = v1.y - v3.y, bz = v1.z - v3.z;
    float d13 = bx * bx + by * by + bz * bz;
    float cx = v2.x - v3.x, cy = v2.y - v3.y, cz = v2.z - v3.z;
    float d23 = cx * cx + cy * cy + cz * cz;

    float m = fminf(fminf(fminf(d01, d02), fminf(d03, d12)), fminf(d13, d23));
    float el = sqrtf(m);
    float alpha = 1.0f - __expf(-d * el);

    __stcs(&tet_area[t], area);    // streaming store: evict-first
    __stcs(&tet_alpha[t], alpha);  // streaming store: evict-first

    // vertex segment-max. d >= 0 so int-bit atomicMax == float max (init 0).
    int db = __float_as_int(d);
    atomicMax(&vert_density_i[idx.x], db);
    atomicMax(&vert_density_i[idx.y], db);
    atomicMax(&vert_density_i[idx.z], db);
    atomicMax(&vert_density_i[idx.w], db);
}

extern "C" void kernel_launch(void* const* d_in, const int* in_sizes, int n_in,
                              void* d_out, int out_size) {
    const float* vertices    = (const float*)d_in[0];
    const int4*  indices     = (const int4*)d_in[1];
    const float* tet_density = (const float*)d_in[2];

    int num_verts = in_sizes[0] / 3;     // 1,000,000
    int num_tets  = in_sizes[2];         // 4,000,000
    if (num_verts > MAX_VERTS) num_verts = MAX_VERTS;  // fixed-shape problem

    float* out = (float*)d_out;
    float* tet_area     = out;
    float* tet_alpha    = out + (size_t)num_tets;
    float* vert_density = out + 2 * (size_t)num_tets;

    // num_verts = 1M is divisible by 4; vd offset (8M floats) is 16B-aligned.
    int num_groups = num_verts / 4;
    prep_kernel<<<(num_groups + 255) / 256, 256>>>(
        (const float4*)vertices, (float4*)vert_density, num_groups);

    int threads = 256;
    int blocks = (num_tets + threads - 1) / threads;
    tet_kernel<<<blocks, threads>>>(indices, tet_density,
                                    tet_area, tet_alpha,
                                    (int*)vert_density, num_tets);
}

// round 15
// speedup vs baseline: 1.0086x; 1.0086x over previous
#include <cuda_runtime.h>

// Problem: tet geometry + vertex segment-max.
// Inputs:  d_in[0] vertices  (V=1,000,000 x 3 f32)
//          d_in[1] indices   (T=4,000,000 x 4 i32)
//          d_in[2] tet_density (T f32)
// Output:  d_out = [tet_area (T) | tet_alpha (T) | vert_density (V)] f32
//
// FINAL. This exact configuration benched 129.1 / 129.5 / 129.6 / 131.3 us
// (stationary noise band +/-1.5us around ~129.8).
// Model (validated R2-R12): tet kernel is pinned at the L2 transaction-count
// roofline — 16M divergent 16B gather wavefronts + 16M spread RED.MAX +
// ~4M streaming transactions vs ~184 LTS slices ~= 120us @ ~92% L2 util.
// Session: 152.1 (scalar gathers) -> 131.9 (float4-padded gather table: 3x
// fewer L1 wavefronts, -25% gather sectors — the structural win) -> ~129.8
// (edge tuning). Falsified: L1 policy (R7 neutral), coarsening (R9 -3.6us),
// memset split (R4 -3us), two-kernel split / read-filtered atomics / dedup /
// compact records / DSMEM (transaction arithmetic).

#define MAX_VERTS 1000000

__device__ float4 g_verts4[MAX_VERTS];

// Prep: pad vertices to float4 AND zero the vert_density output region.
// Each thread: 4 vertices = 3 coalesced float4 loads, 4 float4 stores, 1 zero.
__global__ __launch_bounds__(256) void prep_kernel(const float4* __restrict__ verts4,
                                                   float4* __restrict__ vd4,
                                                   int num_groups) {  // num_verts/4
    int g = blockIdx.x * blockDim.x + threadIdx.x;
    if (g >= num_groups) return;

    float4 a = __ldcs(&verts4[3 * g + 0]);  // v0.x v0.y v0.z v1.x
    float4 b = __ldcs(&verts4[3 * g + 1]);  // v1.y v1.z v2.x v2.y
    float4 c = __ldcs(&verts4[3 * g + 2]);  // v2.z v3.x v3.y v3.z

    g_verts4[4 * g + 0] = make_float4(a.x, a.y, a.z, 0.0f);
    g_verts4[4 * g + 1] = make_float4(a.w, b.x, b.y, 0.0f);
    g_verts4[4 * g + 2] = make_float4(b.z, b.w, c.x, 0.0f);
    g_verts4[4 * g + 3] = make_float4(c.y, c.z, c.w, 0.0f);

    __stcs(&vd4[g], make_float4(0.0f, 0.0f, 0.0f, 0.0f));
}

__global__ __launch_bounds__(256) void tet_kernel(
        const int4* __restrict__ indices,
        const float* __restrict__ tet_density,
        float* __restrict__ tet_area,
        float* __restrict__ tet_alpha,
        int* __restrict__ vert_density_i,  // float bits, all >= 0
        int num_tets) {
    int t = blockIdx.x * blockDim.x + threadIdx.x;
    if (t >= num_tets) return;

    int4 idx = __ldcs(&indices[t]);      // streaming: evict-first
    float d  = __ldcs(&tet_density[t]);  // streaming: evict-first

    // 4 independent 16B gathers -> high MLP, 1 L2 sector each; default policy
    // (policy proven irrelevant in R7; keep L2-resident default).
    float4 v0 = g_verts4[idx.x];
    float4 v1 = g_verts4[idx.y];
    float4 v2 = g_verts4[idx.z];
    float4 v3 = g_verts4[idx.w];

    // det of edge matrix
    float e1x = v1.x - v0.x, e1y = v1.y - v0.y, e1z = v1.z - v0.z;
    float e2x = v2.x - v0.x, e2y = v2.y - v0.y, e2z = v2.z - v0.z;
    float e3x = v3.x - v0.x, e3y = v3.y - v0.y, e3z = v3.z - v0.z;

    float det = e1x * (e2y * e3z - e2z * e3y)
              - e1y * (e2x * e3z - e2z * e3x)
              + e1z * (e2x * e3y - e2y * e3x);
    float area = fabsf(det) * (1.0f / 6.0f);

    // min squared edge length over all 6 edges
    float d01 = e1x * e1x + e1y * e1y + e1z * e1z;
    float d02 = e2x * e2x + e2y * e2y + e2z * e2z;
    float d03 = e3x * e3x + e3y * e3y + e3z * e3z;
    float ax = v1.x - v2.x, ay = v1.y - v2.y, az = v1.z - v2.z;
    float d12 = ax * ax + ay * ay + az * az;
    float bx = v1.x - v3.x, by = v1.y - v3.y, bz = v1.z - v3.z;
    float d13 = bx * bx + by * by + bz * bz;
    float cx = v2.x - v3.x, cy = v2.y - v3.y, cz = v2.z - v3.z;
    float d23 = cx * cx + cy * cy + cz * cz;

    float m = fminf(fminf(fminf(d01, d02), fminf(d03, d12)), fminf(d13, d23));
    float el = sqrtf(m);
    float alpha = 1.0f - __expf(-d * el);

    __stcs(&tet_area[t], area);    // streaming store: evict-first
    __stcs(&tet_alpha[t], alpha);  // streaming store: evict-first

    // vertex segment-max. d >= 0 so int-bit atomicMax == float max (init 0).
    int db = __float_as_int(d);
    atomicMax(&vert_density_i[idx.x], db);
    atomicMax(&vert_density_i[idx.y], db);
    atomicMax(&vert_density_i[idx.z], db);
    atomicMax(&vert_density_i[idx.w], db);
}

extern "C" void kernel_launch(void* const* d_in, const int* in_sizes, int n_in,
                              void* d_out, int out_size) {
    const float* vertices    = (const float*)d_in[0];
    const int4*  indices     = (const int4*)d_in[1];
    const float* tet_density = (const float*)d_in[2];

    int num_verts = in_sizes[0] / 3;     // 1,000,000
    int num_tets  = in_sizes[2];         // 4,000,000
    if (num_verts > MAX_VERTS) num_verts = MAX_VERTS;  // fixed-shape problem

    float* out = (float*)d_out;
    float* tet_area     = out;
    float* tet_alpha    = out + (size_t)num_tets;
    float* vert_density = out + 2 * (size_t)num_tets;

    // num_verts = 1M is divisible by 4; vd offset (8M floats) is 16B-aligned.
    int num_groups = num_verts / 4;
    prep_kernel<<<(num_groups + 255) / 256, 256>>>(
        (const float4*)vertices, (float4*)vert_density, num_groups);

    int threads = 256;
    int blocks = (num_tets + threads - 1) / threads;
    tet_kernel<<<blocks, threads>>>(indices, tet_density,
                                    tet_area, tet_alpha,
                                    (int*)vert_density, num_tets);
}

// round 16
// speedup vs baseline: 1.0299x; 1.0211x over previous
#include <cuda_runtime.h>

// Problem: tet geometry + vertex segment-max.
// Inputs:  d_in[0] vertices  (V=1,000,000 x 3 f32)
//          d_in[1] indices   (T=4,000,000 x 4 i32)
//          d_in[2] tet_density (T f32)
// Output:  d_out = [tet_area (T) | tet_alpha (T) | vert_density (V)] f32
//
// FINAL. This exact configuration benched 129.1/129.5/129.6/130.1/131.3 us
// across six runs (stationary noise +/-1.5us around ~129.8).
// Model (validated R2-R14): tet kernel is pinned at the L2 transaction-count
// roofline — 16M divergent 16B gather wavefronts + 16M spread RED.MAX +
// ~4M streaming transactions vs ~184 LTS slices ~= 120us @ ~92% L2 util.
// Session: 152.1 (scalar gathers) -> 131.9 (float4-padded gather table: 3x
// fewer L1 wavefronts, -25% gather sectors — the structural win) -> ~129.8.
// Falsified: L1 policy (R7 neutral -> count-bound), coarsening (R9 -3.6us),
// memset split (R4 -3us), half-precision records (count-bound + error
// amplification), shadow atomic arrays / two-kernel split / read-filtered
// atomics / dedup / DSMEM (transaction arithmetic).

#define MAX_VERTS 1000000

__device__ float4 g_verts4[MAX_VERTS];

// Prep: pad vertices to float4 AND zero the vert_density output region.
// Each thread: 4 vertices = 3 coalesced float4 loads, 4 float4 stores, 1 zero.
__global__ __launch_bounds__(256) void prep_kernel(const float4* __restrict__ verts4,
                                                   float4* __restrict__ vd4,
                                                   int num_groups) {  // num_verts/4
    int g = blockIdx.x * blockDim.x + threadIdx.x;
    if (g >= num_groups) return;

    float4 a = __ldcs(&verts4[3 * g + 0]);  // v0.x v0.y v0.z v1.x
    float4 b = __ldcs(&verts4[3 * g + 1]);  // v1.y v1.z v2.x v2.y
    float4 c = __ldcs(&verts4[3 * g + 2]);  // v2.z v3.x v3.y v3.z

    g_verts4[4 * g + 0] = make_float4(a.x, a.y, a.z, 0.0f);
    g_verts4[4 * g + 1] = make_float4(a.w, b.x, b.y, 0.0f);
    g_verts4[4 * g + 2] = make_float4(b.z, b.w, c.x, 0.0f);
    g_verts4[4 * g + 3] = make_float4(c.y, c.z, c.w, 0.0f);

    __stcs(&vd4[g], make_float4(0.0f, 0.0f, 0.0f, 0.0f));
}

__global__ __launch_bounds__(256) void tet_kernel(
        const int4* __restrict__ indices,
        const float* __restrict__ tet_density,
        float* __restrict__ tet_area,
        float* __restrict__ tet_alpha,
        int* __restrict__ vert_density_i,  // float bits, all >= 0
        int num_tets) {
    int t = blockIdx.x * blockDim.x + threadIdx.x;
    if (t >= num_tets) return;

    int4 idx = __ldcs(&indices[t]);      // streaming: evict-first
    float d  = __ldcs(&tet_density[t]);  // streaming: evict-first

    // 4 independent 16B gathers -> high MLP, 1 L2 sector each; default policy
    // (policy proven irrelevant in R7; keep L2-resident default).
    float4 v0 = g_verts4[idx.x];
    float4 v1 = g_verts4[idx.y];
    float4 v2 = g_verts4[idx.z];
    float4 v3 = g_verts4[idx.w];

    // det of edge matrix
    float e1x = v1.x - v0.x, e1y = v1.y - v0.y, e1z = v1.z - v0.z;
    float e2x = v2.x - v0.x, e2y = v2.y - v0.y, e2z = v2.z - v0.z;
    float e3x = v3.x - v0.x, e3y = v3.y - v0.y, e3z = v3.z - v0.z;

    float det = e1x * (e2y * e3z - e2z * e3y)
              - e1y * (e2x * e3z - e2z * e3x)
              + e1z * (e2x * e3y - e2y * e3x);
    float area = fabsf(det) * (1.0f / 6.0f);

    // min squared edge length over all 6 edges
    float d01 = e1x * e1x + e1y * e1y + e1z * e1z;
    float d02 = e2x * e2x + e2y * e2y + e2z * e2z;
    float d03 = e3x * e3x + e3y * e3y + e3z * e3z;
    float ax = v1.x - v2.x, ay = v1.y - v2.y, az = v1.z - v2.z;
    float d12 = ax * ax + ay * ay + az * az;
    float bx = v1.x - v3.x, by = v1.y - v3.y, bz = v1.z - v3.z;
    float d13 = bx * bx + by * by + bz * bz;
    float cx = v2.x - v3.x, cy = v2.y - v3.y, cz = v2.z - v3.z;
    float d23 = cx * cx + cy * cy + cz * cz;

    float m = fminf(fminf(fminf(d01, d02), fminf(d03, d12)), fminf(d13, d23));
    float el = sqrtf(m);
    float alpha = 1.0f - __expf(-d * el);

    __stcs(&tet_area[t], area);    // streaming store: evict-first
    __stcs(&tet_alpha[t], alpha);  // streaming store: evict-first

    // vertex segment-max. d >= 0 so int-bit atomicMax == float max (init 0).
    int db = __float_as_int(d);
    atomicMax(&vert_density_i[idx.x], db);
    atomicMax(&vert_density_i[idx.y], db);
    atomicMax(&vert_density_i[idx.z], db);
    atomicMax(&vert_density_i[idx.w], db);
}

extern "C" void kernel_launch(void* const* d_in, const int* in_sizes, int n_in,
                              void* d_out, int out_size) {
    const float* vertices    = (const float*)d_in[0];
    const int4*  indices     = (const int4*)d_in[1];
    const float* tet_density = (const float*)d_in[2];

    int num_verts = in_sizes[0] / 3;     // 1,000,000
    int num_tets  = in_sizes[2];         // 4,000,000
    if (num_verts > MAX_VERTS) num_verts = MAX_VERTS;  // fixed-shape problem

    float* out = (float*)d_out;
    float* tet_area     = out;
    float* tet_alpha    = out + (size_t)num_tets;
    float* vert_density = out + 2 * (size_t)num_tets;

    // num_verts = 1M is divisible by 4; vd offset (8M floats) is 16B-aligned.
    int num_groups = num_verts / 4;
    prep_kernel<<<(num_groups + 255) / 256, 256>>>(
        (const float4*)vertices, (float4*)vert_density, num_groups);

    int threads = 256;
    int blocks = (num_tets + threads - 1) / threads;
    tet_kernel<<<blocks, threads>>>(indices, tet_density,
                                    tet_area, tet_alpha,
                                    (int*)vert_density, num_tets);
}